// round 13
// baseline (speedup 1.0000x reference)
#include <cuda_runtime.h>

typedef unsigned long long ull;

#define BB   256
#define TT   2000
#define FIN  42
#define FINP 44
#define HH   24
#define G3   72
#define ROWS (BB * TT)
#define UU   4

// scratch: xg[row][72] gate preacts (147.5 MB), h[B,T,24] (49 MB)
__device__ float g_xg[(size_t)ROWS * G3];
__device__ float g_h[(size_t)ROWS * HH];

__device__ __forceinline__ float tanh_a(float x) {
    float y; asm("tanh.approx.f32 %0, %1;" : "=f"(y) : "f"(x)); return y;
}
__device__ __forceinline__ ull fma2(ull a, ull b, ull c) {
    ull d; asm("fma.rn.f32x2 %0, %1, %2, %3;" : "=l"(d) : "l"(a), "l"(b), "l"(c)); return d;
}
__device__ __forceinline__ ull add2(ull a, ull b) {
    ull d; asm("add.rn.f32x2 %0, %1, %2;" : "=l"(d) : "l"(a), "l"(b)); return d;
}
__device__ __forceinline__ ull pack2(float lo, float hi) {
    ull d; asm("mov.b64 %0, {%1, %2};" : "=l"(d) : "f"(lo), "f"(hi)); return d;
}
__device__ __forceinline__ float2 unpack2(ull v) {
    float2 r; asm("mov.b64 {%0, %1}, %2;" : "=f"(r.x), "=f"(r.y) : "l"(v)); return r;
}
__device__ __forceinline__ float hsum2(ull v) {
    float2 r = unpack2(v); return r.x + r.y;
}
__device__ __forceinline__ void sts_f32(unsigned addr, float v) {
    asm volatile("st.shared.f32 [%0], %1;" :: "r"(addr), "f"(v) : "memory");
}
__device__ __forceinline__ void lds_v4(unsigned addr, ull& a, ull& b) {
    asm volatile("ld.shared.v4.b32 {%0, %1, %2, %3}, [%4];"
                 : "=r"(*(unsigned*)&a), "=r"(((unsigned*)&a)[1]),
                   "=r"(*(unsigned*)&b), "=r"(((unsigned*)&b)[1])
                 : "r"(addr) : "memory");
}

// ---------------------------------------------------------------------------
// Phase 1: compact [row][72] layout. 2 rows/thread; x direct from global
// (LDG.64, coalesced). Biases folded: r/z entries stored as
// 0.5*(x-side + b_hh) with W rows pre-halved; n entries plain x-side + b_ih.
// ---------------------------------------------------------------------------
__global__ __launch_bounds__(128) void vad_phase1(
    const float* __restrict__ x, const float* __restrict__ lc1_w,
    const float* __restrict__ lc1_b, const float* __restrict__ w_ih,
    const float* __restrict__ b_ih, const float* __restrict__ b_hh)
{
    __shared__ __align__(16) float s_w1[HH * FINP];
    __shared__ float s_b1[HH];
    __shared__ __align__(16) ull s_wi2[G3 * 12];
    __shared__ float s_cb[G3];

    int tid = threadIdx.x;
    for (int i = tid; i < HH * FINP; i += 128) {
        int h = i / FINP, f = i - h * FINP;
        s_w1[i] = (f < FIN) ? lc1_w[h * FIN + f] : 0.0f;
    }
    const ull* wi8 = (const ull*)w_ih;
    for (int i = tid; i < G3 * 12; i += 128) {
        ull w = wi8[i];
        if (i < 48 * 12) {                 // r,z rows pre-halved
            float2 f = unpack2(w);
            w = pack2(0.5f * f.x, 0.5f * f.y);
        }
        s_wi2[i] = w;
    }
    if (tid < G3) {
        float b = b_ih[tid];
        s_cb[tid] = (tid < 48) ? 0.5f * (b + b_hh[tid]) : b;
    }
    if (tid < HH) s_b1[tid] = lc1_b[tid];
    __syncthreads();

    size_t r0 = (size_t)blockIdx.x * 256;
    const ull* xA = (const ull*)(x + (r0 + tid) * FIN);
    const ull* xB = (const ull*)(x + (r0 + 128 + tid) * FIN);

    ull xpA[22], xpB[22];
#pragma unroll
    for (int q = 0; q < 21; q++) { xpA[q] = xA[q]; xpB[q] = xB[q]; }
    xpA[21] = 0ULL; xpB[21] = 0ULL;

    float aA[HH], aB[HH];
#pragma unroll
    for (int h = 0; h < HH; h++) {
        const ulonglong2* wv = (const ulonglong2*)&s_w1[h * FINP];
        float b = s_b1[h];
        ull pA = pack2(b, 0.0f), qA = 0ULL, pB = pack2(b, 0.0f), qB = 0ULL;
#pragma unroll
        for (int m = 0; m < 11; m++) {
            ulonglong2 w = wv[m];
            pA = fma2(w.x, xpA[2 * m], pA);
            qA = fma2(w.y, xpA[2 * m + 1], qA);
            pB = fma2(w.x, xpB[2 * m], pB);
            qB = fma2(w.y, xpB[2 * m + 1], qB);
        }
        aA[h] = tanh_a(hsum2(add2(pA, qA)));
        aB[h] = tanh_a(hsum2(add2(pB, qB)));
    }

    ull a2A[12], a2B[12];
#pragma unroll
    for (int k = 0; k < 12; k++) {
        a2A[k] = pack2(aA[2 * k], aA[2 * k + 1]);
        a2B[k] = pack2(aB[2 * k], aB[2 * k + 1]);
    }

    float4* outA = (float4*)(g_xg + (r0 + tid) * G3);
    float4* outB = (float4*)(g_xg + (r0 + 128 + tid) * G3);
#pragma unroll
    for (int g4 = 0; g4 < 18; g4++) {
        float oA[4], oB[4];
#pragma unroll
        for (int s = 0; s < 4; s++) {
            int g = g4 * 4 + s;
            const ulonglong2* w2 = (const ulonglong2*)&s_wi2[g * 12];
            float b = s_cb[g];
            ull pA = pack2(b, 0.0f), qA = 0ULL, pB = pack2(b, 0.0f), qB = 0ULL;
#pragma unroll
            for (int m = 0; m < 6; m++) {
                ulonglong2 w = w2[m];
                pA = fma2(w.x, a2A[2 * m], pA);
                qA = fma2(w.y, a2A[2 * m + 1], qA);
                pB = fma2(w.x, a2B[2 * m], pB);
                qB = fma2(w.y, a2B[2 * m + 1], qB);
            }
            oA[s] = hsum2(add2(pA, qA));
            oB[s] = hsum2(add2(pB, qB));
        }
        outA[g4] = make_float4(oA[0], oA[1], oA[2], oA[3]);
        outB[g4] = make_float4(oB[0], oB[1], oB[2], oB[3]);
    }
}

// ---------------------------------------------------------------------------
// Phase 2: GRU recurrence, TWO batch rows per warp. The two rows' serial
// chains are independent, so row B's instructions issue under row A's
// latency (and vice versa) — the spine becomes issue-bound. W_hh registers
// are shared between the rows. Single fma2 chain per gate (depth hidden by
// the interleave). Sync-free double-buffered smem broadcast per row.
// ---------------------------------------------------------------------------
__global__ __launch_bounds__(32) void vad_phase2(
    const float* __restrict__ w_hh, const float* __restrict__ b_hh)
{
    __shared__ __align__(16) float s_h[2][2][32];   // [buf][row][lane]
    int lane = threadIdx.x;
    int bA = blockIdx.x * 2, bB = bA + 1;
    int i = (lane < HH) ? lane : 0;

    unsigned sbase;
    asm("{ .reg .u64 t; cvta.to.shared.u64 t, %1; cvt.u32.u64 %0, t; }"
        : "=r"(sbase) : "l"(&s_h[0][0][0]));

    const ull* w8 = (const ull*)w_hh;
    ull wr2[12], wz2[12], wn2[12];
#pragma unroll
    for (int k = 0; k < 12; k++) {
        float2 r = unpack2(w8[(0 * HH + i) * 12 + k]);
        wr2[k] = pack2(0.5f * r.x, 0.5f * r.y);
        float2 z = unpack2(w8[(1 * HH + i) * 12 + k]);
        wz2[k] = pack2(0.5f * z.x, 0.5f * z.y);
        wn2[k] = w8[(2 * HH + i) * 12 + k];
    }
    ull bn2 = pack2(b_hh[2 * HH + i], 0.0f);

    const float* xgA = g_xg + (size_t)bA * TT * G3;
    const float* xgB = g_xg + (size_t)bB * TT * G3;
    float* hpA = g_h + (size_t)bA * TT * HH;
    float* hpB = g_h + (size_t)bB * TT * HH;

    float hA = 0.0f, hB = 0.0f;
    float crA[UU], czA[UU], cnA[UU], crB[UU], czB[UU], cnB[UU];
#pragma unroll
    for (int u = 0; u < UU; u++) {
        crA[u] = __ldcg(xgA + u * G3 + 0 * HH + i);
        czA[u] = __ldcg(xgA + u * G3 + 1 * HH + i);
        cnA[u] = __ldcg(xgA + u * G3 + 2 * HH + i);
        crB[u] = __ldcg(xgB + u * G3 + 0 * HH + i);
        czB[u] = __ldcg(xgB + u * G3 + 1 * HH + i);
        cnB[u] = __ldcg(xgB + u * G3 + 2 * HH + i);
    }

    for (int t0 = 0; t0 < TT; t0 += UU) {
        float nrA[UU], nzA[UU], nnA[UU], nrB[UU], nzB[UU], nnB[UU];
        bool more = (t0 + UU) < TT;
        const float* npA = xgA + (size_t)(t0 + UU) * G3;
        const float* npB = xgB + (size_t)(t0 + UU) * G3;
#pragma unroll
        for (int u = 0; u < UU; u++) {
            nrA[u] = more ? __ldcg(npA + u * G3 + 0 * HH + i) : 0.0f;
            nzA[u] = more ? __ldcg(npA + u * G3 + 1 * HH + i) : 0.0f;
            nnA[u] = more ? __ldcg(npA + u * G3 + 2 * HH + i) : 0.0f;
            nrB[u] = more ? __ldcg(npB + u * G3 + 0 * HH + i) : 0.0f;
            nzB[u] = more ? __ldcg(npB + u * G3 + 1 * HH + i) : 0.0f;
            nnB[u] = more ? __ldcg(npB + u * G3 + 2 * HH + i) : 0.0f;
        }

#pragma unroll
        for (int u = 0; u < UU; u++) {
            unsigned off = (u & 1) ? 256u : 0u;
            sts_f32(sbase + off + lane * 4, hA);           // ordered (in-order LSU,
            sts_f32(sbase + off + 128 + lane * 4, hB);     //  converged warp)
            ull h2A[12], h2B[12];
#pragma unroll
            for (int k = 0; k < 6; k++) {
                lds_v4(sbase + off + k * 16, h2A[2 * k], h2A[2 * k + 1]);
                lds_v4(sbase + off + 128 + k * 16, h2B[2 * k], h2B[2 * k + 1]);
            }

            ull raA = pack2(crA[u], 0.0f), zaA = pack2(czA[u], 0.0f), naA = bn2;
            ull raB = pack2(crB[u], 0.0f), zaB = pack2(czB[u], 0.0f), naB = bn2;
#pragma unroll
            for (int m = 0; m < 12; m++) {
                raA = fma2(wr2[m], h2A[m], raA);
                raB = fma2(wr2[m], h2B[m], raB);
                zaA = fma2(wz2[m], h2A[m], zaA);
                zaB = fma2(wz2[m], h2B[m], zaB);
                naA = fma2(wn2[m], h2A[m], naA);
                naB = fma2(wn2[m], h2B[m], naB);
            }
            float hrA = hsum2(raA), hzA = hsum2(zaA), hnA = hsum2(naA);
            float hrB = hsum2(raB), hzB = hsum2(zaB), hnB = hsum2(naB);

            float rA = fmaf(tanh_a(hrA), 0.5f, 0.5f);
            float rB = fmaf(tanh_a(hrB), 0.5f, 0.5f);
            float zA = fmaf(tanh_a(hzA), 0.5f, 0.5f);
            float zB = fmaf(tanh_a(hzB), 0.5f, 0.5f);
            float nA = tanh_a(fmaf(rA, hnA, cnA[u]));
            float nB = tanh_a(fmaf(rB, hnB, cnB[u]));
            hA = fmaf(zA, hA - nA, nA);
            hB = fmaf(zB, hB - nB, nB);

            if (lane < HH) {
                hpA[(t0 + u) * HH + lane] = hA;
                hpB[(t0 + u) * HH + lane] = hB;
            }
        }

#pragma unroll
        for (int u = 0; u < UU; u++) {
            crA[u] = nrA[u]; czA[u] = nzA[u]; cnA[u] = nnA[u];
            crB[u] = nrB[u]; czB[u] = nzB[u]; cnB[u] = nnB[u];
        }
    }
}

// ---------------------------------------------------------------------------
// Phase 3: out[b,t] = sigmoid(lc2_w . h[b,t,:] + lc2_b). One thread per row.
// ---------------------------------------------------------------------------
__global__ __launch_bounds__(256) void vad_phase3(
    const float* __restrict__ lc2_w, const float* __restrict__ lc2_b,
    float* __restrict__ out)
{
    size_t idx = (size_t)blockIdx.x * 256 + threadIdx.x;
    const float4* hv = (const float4*)(g_h + idx * HH);
    const float4* wv = (const float4*)lc2_w;

    ull acc = pack2(0.5f * lc2_b[0], 0.0f);
#pragma unroll
    for (int q = 0; q < 6; q++) {
        float4 hq = hv[q];
        float4 wq = __ldg(&wv[q]);
        acc = fma2(pack2(hq.x, hq.y), pack2(0.5f * wq.x, 0.5f * wq.y), acc);
        acc = fma2(pack2(hq.z, hq.w), pack2(0.5f * wq.z, 0.5f * wq.w), acc);
    }
    out[idx] = fmaf(tanh_a(hsum2(acc)), 0.5f, 0.5f);
}

extern "C" void kernel_launch(void* const* d_in, const int* in_sizes, int n_in,
                              void* d_out, int out_size) {
    const float* x     = (const float*)d_in[0];
    const float* lc1_w = (const float*)d_in[1];
    const float* lc1_b = (const float*)d_in[2];
    const float* w_ih  = (const float*)d_in[3];
    const float* w_hh  = (const float*)d_in[4];
    const float* b_ih  = (const float*)d_in[5];
    const float* b_hh  = (const float*)d_in[6];
    const float* lc2_w = (const float*)d_in[7];
    const float* lc2_b = (const float*)d_in[8];
    float* out = (float*)d_out;

    vad_phase1<<<ROWS / 256, 128>>>(x, lc1_w, lc1_b, w_ih, b_ih, b_hh);
    vad_phase2<<<BB / 2, 32>>>(w_hh, b_hh);
    vad_phase3<<<ROWS / 256, 256>>>(lc2_w, lc2_b, out);
}